// round 2
// baseline (speedup 1.0000x reference)
#include <cuda_runtime.h>

// QuantumAutoencoder: reference's reshape(B,3,8,8,4,4).mean((-1,-2)).mean(1)
// == mean over 16 CONTIGUOUS floats per patch per channel (strip pooling),
// then angle = v/255*pi - pi/2, out = cos(angle).
// In: [32768,3,32,32] f32. Out: [32768,64] f32.

#define PI_F 3.14159265358979323846f

__global__ void __launch_bounds__(256) qae_kernel(const float* __restrict__ in,
                                                  float* __restrict__ out,
                                                  int n_img) {
    int tid = blockIdx.x * blockDim.x + threadIdx.x;
    int img = tid >> 6;          // 64 outputs per image
    if (img >= n_img) return;
    int patch = tid & 63;        // 0..63 -> strip of 16 contiguous floats

    // per-channel base, in float4 units (256 float4 per 1024-float channel)
    const float4* base = reinterpret_cast<const float4*>(in) +
                         (size_t)img * 3 * 256 + patch * 4;

    float s = 0.0f;
    #pragma unroll
    for (int c = 0; c < 3; ++c) {
        const float4* pc = base + c * 256;
        #pragma unroll
        for (int j = 0; j < 4; ++j) {
            float4 v = __ldg(pc + j);
            s += (v.x + v.y) + (v.z + v.w);
        }
    }
    float mean = s * (1.0f / 48.0f);
    float ang = mean * (PI_F / 255.0f) - (PI_F * 0.5f);
    out[tid] = cosf(ang);
}

extern "C" void kernel_launch(void* const* d_in, const int* in_sizes, int n_in,
                              void* d_out, int out_size) {
    const float* in = (const float*)d_in[0];
    float* out = (float*)d_out;
    int n_img = in_sizes[0] / (3 * 32 * 32);   // 32768
    int total = n_img * 64;
    int threads = 256;
    int blocks = (total + threads - 1) / threads;
    qae_kernel<<<blocks, threads>>>(in, out, n_img);
}

// round 3
// speedup vs baseline: 1.0147x; 1.0147x over previous
#include <cuda_runtime.h>

// QuantumAutoencoder strip-pool + cos. In: [32768,3,32,32] f32 -> Out: [32768,64] f32.
// Fully-coalesced layout: per image, float4-slot t (0..255) is the same spatial
// position in each of the 3 channels (offsets t, t+256, t+512 in float4 units).
// Patch p (0..63) = slots 4p..4p+3 -> 2-step shfl_xor reduce over 4 lanes.

#define PI_F 3.14159265358979323846f
#define IMGS_PER_BLOCK 2

__global__ void __launch_bounds__(256) qae_kernel(const float4* __restrict__ in,
                                                  float* __restrict__ out,
                                                  int n_img) {
    int t = threadIdx.x;                       // 0..255
    int img0 = blockIdx.x * IMGS_PER_BLOCK;

    float s[IMGS_PER_BLOCK];
    #pragma unroll
    for (int i = 0; i < IMGS_PER_BLOCK; ++i) {
        const float4* p = in + (size_t)(img0 + i) * 768;  // 3*1024/4
        float4 a = __ldg(p + t);
        float4 b = __ldg(p + t + 256);
        float4 c = __ldg(p + t + 512);
        s[i] = ((a.x + a.y) + (a.z + a.w))
             + ((b.x + b.y) + (b.z + b.w))
             + ((c.x + c.y) + (c.z + c.w));
    }

    #pragma unroll
    for (int i = 0; i < IMGS_PER_BLOCK; ++i) {
        float v = s[i];
        v += __shfl_xor_sync(0xffffffffu, v, 1);
        v += __shfl_xor_sync(0xffffffffu, v, 2);
        if ((t & 3) == 0) {
            float mean = v * (1.0f / 48.0f);
            float ang = mean * (PI_F / 255.0f) - (PI_F * 0.5f);
            out[(size_t)(img0 + i) * 64 + (t >> 2)] = cosf(ang);
        }
    }
}

extern "C" void kernel_launch(void* const* d_in, const int* in_sizes, int n_in,
                              void* d_out, int out_size) {
    const float4* in = (const float4*)d_in[0];
    float* out = (float*)d_out;
    int n_img = in_sizes[0] / (3 * 32 * 32);     // 32768
    int blocks = n_img / IMGS_PER_BLOCK;         // 16384
    qae_kernel<<<blocks, 256>>>(in, out, n_img);
}